// round 16
// baseline (speedup 1.0000x reference)
#include <cuda_runtime.h>
#include <cuda_bf16.h>
#include <math.h>
#include <float.h>
#include <stdint.h>

// Problem constants
#define BATCH 2
#define SEQ   2048
#define DMODEL 2048
#define NH    32
#define NKV   8
#define REP   4
#define HD    64
#define TOKENS (BATCH*SEQ)   // 4096
#define QDIM  (NH*HD)        // 2048
#define KVDIM (NKV*HD)       // 512

// Scratch (device globals: allocation-free)
__device__ __nv_bfloat16 g_Qhb[TOKENS*QDIM],  g_Qlb[TOKENS*QDIM];   // pre-scaled bf16 split Q
__device__ __nv_bfloat16 g_Khb[TOKENS*KVDIM], g_Klb[TOKENS*KVDIM];
__device__ __nv_bfloat16 g_Vhb[TOKENS*KVDIM], g_Vlb[TOKENS*KVDIM];
// fragment-packed, tf32-rounded GEMM operands
__device__ float g_xp[TOKENS*DMODEL];
__device__ float g_wqp[DMODEL*QDIM];
__device__ float g_wkp[DMODEL*KVDIM];
__device__ float g_wvp[DMODEL*KVDIM];
__device__ float g_wop[QDIM*DMODEL];
__device__ float g_Apk[TOKENS*QDIM];   // written directly by flash epilogue
__device__ float g_cos[SEQ*(HD/2)];
__device__ float g_sin[SEQ*(HD/2)];

__device__ __forceinline__ uint32_t f2tf32(float x) {
    uint32_t r;
    asm("cvt.rna.tf32.f32 %0, %1;" : "=r"(r) : "f"(x));
    return r;
}
__device__ __forceinline__ float tf32f(float x) {
    return __uint_as_float(f2tf32(x));
}
__device__ __forceinline__ void mma_tf32(float* c, const uint32_t* a, uint32_t b0, uint32_t b1) {
    asm volatile("mma.sync.aligned.m16n8k8.row.col.f32.tf32.tf32.f32 "
                 "{%0,%1,%2,%3}, {%4,%5,%6,%7}, {%8,%9}, {%0,%1,%2,%3};"
                 : "+f"(c[0]), "+f"(c[1]), "+f"(c[2]), "+f"(c[3])
                 : "r"(a[0]), "r"(a[1]), "r"(a[2]), "r"(a[3]), "r"(b0), "r"(b1));
}
__device__ __forceinline__ void mma_bf16(float* c, const uint32_t* a, uint32_t b0, uint32_t b1) {
    asm volatile("mma.sync.aligned.m16n8k16.row.col.f32.bf16.bf16.f32 "
                 "{%0,%1,%2,%3}, {%4,%5,%6,%7}, {%8,%9}, {%0,%1,%2,%3};"
                 : "+f"(c[0]), "+f"(c[1]), "+f"(c[2]), "+f"(c[3])
                 : "r"(a[0]), "r"(a[1]), "r"(a[2]), "r"(a[3]), "r"(b0), "r"(b1));
}
__device__ __forceinline__ void ldmx4(uint32_t* r, uint32_t addr) {
    asm volatile("ldmatrix.sync.aligned.m8n8.x4.shared.b16 {%0,%1,%2,%3}, [%4];"
                 : "=r"(r[0]), "=r"(r[1]), "=r"(r[2]), "=r"(r[3]) : "r"(addr));
}
__device__ __forceinline__ void ldmx4t(uint32_t* r, uint32_t addr) {
    asm volatile("ldmatrix.sync.aligned.m8n8.x4.trans.shared.b16 {%0,%1,%2,%3}, [%4];"
                 : "=r"(r[0]), "=r"(r[1]), "=r"(r[2]), "=r"(r[3]) : "r"(addr));
}
__device__ __forceinline__ void cp_async16(void* smem_dst, const void* gmem_src) {
    uint32_t s = (uint32_t)__cvta_generic_to_shared(smem_dst);
    asm volatile("cp.async.cg.shared.global [%0], [%1], 16;" :: "r"(s), "l"(gmem_src));
}
__device__ __forceinline__ void cp_commit() {
    asm volatile("cp.async.commit_group;");
}
template<int N> __device__ __forceinline__ void cp_wait() {
    asm volatile("cp.async.wait_group %0;" :: "n"(N));
}
__device__ __forceinline__ uint32_t pack_bf16(float a, float b, float* ra, float* rb) {
    __nv_bfloat16 ha = __float2bfloat16(a);
    __nv_bfloat16 hb = __float2bfloat16(b);
    *ra = a - __bfloat162float(ha);
    *rb = b - __bfloat162float(hb);
    uint32_t lo = (uint32_t)__bfloat16_as_ushort(ha);
    uint32_t hi = (uint32_t)__bfloat16_as_ushort(hb);
    return lo | (hi << 16);
}

// ---------------------------------------------------------------------------
// Fragment packers (include tf32 rounding).
// ---------------------------------------------------------------------------
__global__ void packA_kernel(const float* __restrict__ in, float* __restrict__ out,
                             int R, int C) {
    int idx = blockIdx.x * blockDim.x + threadIdx.x;
    int total = (R >> 4) * (C >> 3) * 32;
    if (idx >= total) return;
    int l  = idx & 31;
    int t2 = idx >> 5;
    int Kb = t2 % (C >> 3);
    int Mb = t2 / (C >> 3);
    int g = l >> 2, tg = l & 3;
    const float* src = in + (size_t)(Mb*16 + g)*C + Kb*8 + tg;
    float4 v;
    v.x = tf32f(src[0]);
    v.y = tf32f(src[(size_t)8*C]);
    v.z = tf32f(src[4]);
    v.w = tf32f(src[(size_t)8*C + 4]);
    *(float4*)(out + (size_t)idx*4) = v;
}

__global__ void packB_kernel(const float* __restrict__ in, float* __restrict__ out,
                             int K, int N) {
    int idx = blockIdx.x * blockDim.x + threadIdx.x;
    int total = (N >> 3) * (K >> 4) * 32;
    if (idx >= total) return;
    int l  = idx & 31;
    int t2 = idx >> 5;
    int Kp = t2 % (K >> 4);
    int Nb = t2 / (K >> 4);
    int g = l >> 2, tg = l & 3;
    const float* src = in + (size_t)(Kp*16 + tg)*N + Nb*8 + g;
    float4 v;
    v.x = tf32f(src[0]);
    v.y = tf32f(src[(size_t)4*N]);
    v.z = tf32f(src[(size_t)8*N]);
    v.w = tf32f(src[(size_t)12*N]);
    *(float4*)(out + (size_t)idx*4) = v;
}

// ---------------------------------------------------------------------------
// RoPE tables
// ---------------------------------------------------------------------------
__global__ void rope_table_kernel() {
    int idx = blockIdx.x * blockDim.x + threadIdx.x;
    if (idx >= SEQ*(HD/2)) return;
    int pos = idx >> 5;
    int i   = idx & 31;
    double expo = (2.0 * i) / 64.0;
    float invf = (float)(1.0 / pow(10000.0, expo));
    float fr = (float)pos * invf;
    double a = (double)fr;
    g_cos[idx] = (float)cos(a);
    g_sin[idx] = (float)sin(a);
}

// ---------------------------------------------------------------------------
// Pipelined tf32 GEMM on fragment-packed operands, BK=32.
//   mode bit0: RoPE   bit1: scale 0.125   bit2: split into bf16 hi/lo (Chb,Clb)
// smem/stage: A 4096 floats ([mb8][k8x4][lane][4]), B 4096 ([nb16][k16x2][lane][4]).
// ---------------------------------------------------------------------------
#define GK 2048
#define NSTG 3
#define ASTG2 4096
#define BSTG2 4096
#define GEMM_SMEM (NSTG*(ASTG2+BSTG2)*4)   // 98304 B

__device__ __forceinline__ void gemm_body(const float* __restrict__ Apk,
                                          const float* __restrict__ Bpk,
                                          float* __restrict__ Cf,
                                          __nv_bfloat16* __restrict__ Chb,
                                          __nv_bfloat16* __restrict__ Clb,
                                          int N, int by, int cb, int mode) {
    extern __shared__ float sm[];
    float* As = sm;
    float* Bs = sm + NSTG*ASTG2;

    int tid  = threadIdx.x;
    int lane = tid & 31, warp = tid >> 5;
    int wm = warp & 3, wn = warp >> 2;
    int m_warp = wm * 32, n_warp = wn * 64;
    int g  = lane >> 2;
    int tg = lane & 3;

    int a_mb = tid >> 5, a_l = tid & 31;     // A: 8 m-blocks x 32 lanes
    int b_nb = tid >> 4, b_sub = tid & 15;   // B: 16 n-blocks x 16 subs

    const float* Abase = Apk + (((size_t)(by*8 + a_mb))*(GK/8))*128 + a_l*4;
    const float* Bbase = Bpk + (((size_t)(cb*16 + b_nb))*(GK/16))*128 + b_sub*8;

    float acc[2][8][4];
    #pragma unroll
    for (int mi = 0; mi < 2; mi++)
        #pragma unroll
        for (int ni = 0; ni < 8; ni++)
            #pragma unroll
            for (int c = 0; c < 4; c++) acc[mi][ni][c] = 0.f;

    #pragma unroll
    for (int s = 0; s < NSTG-1; s++) {
        float* as = As + s*ASTG2;
        float* bs = Bs + s*BSTG2;
        #pragma unroll
        for (int q = 0; q < 4; q++)
            cp_async16(&as[a_mb*512 + q*128 + a_l*4], Abase + (size_t)(4*s + q)*128);
        #pragma unroll
        for (int q = 0; q < 2; q++) {
            cp_async16(&bs[b_nb*256 + q*128 + b_sub*8],     Bbase + (size_t)(2*s + q)*128);
            cp_async16(&bs[b_nb*256 + q*128 + b_sub*8 + 4], Bbase + (size_t)(2*s + q)*128 + 4);
        }
        cp_commit();
    }

    const int NITER = GK / 32;   // 64
    int s = 0;
    for (int it = 0; it < NITER; it++) {
        cp_wait<NSTG-2>();
        __syncthreads();

        int itpre = it + NSTG - 1;
        if (itpre < NITER) {
            int sp = itpre % NSTG;
            float* as = As + sp*ASTG2;
            float* bs = Bs + sp*BSTG2;
            #pragma unroll
            for (int q = 0; q < 4; q++)
                cp_async16(&as[a_mb*512 + q*128 + a_l*4], Abase + (size_t)(4*itpre + q)*128);
            #pragma unroll
            for (int q = 0; q < 2; q++) {
                cp_async16(&bs[b_nb*256 + q*128 + b_sub*8],     Bbase + (size_t)(2*itpre + q)*128);
                cp_async16(&bs[b_nb*256 + q*128 + b_sub*8 + 4], Bbase + (size_t)(2*itpre + q)*128 + 4);
            }
        }
        cp_commit();

        const float* as = As + s*ASTG2;
        const float* bs = Bs + s*BSTG2;

        #pragma unroll
        for (int q16 = 0; q16 < 2; q16++) {
            float4 bv[8];
            #pragma unroll
            for (int ni = 0; ni < 8; ni++)
                bv[ni] = *(const float4*)(bs + (n_warp/8 + ni)*256 + q16*128 + lane*4);

            #pragma unroll
            for (int kk8 = 0; kk8 < 2; kk8++) {
                uint32_t afr[2][4];
                #pragma unroll
                for (int mi = 0; mi < 2; mi++) {
                    float4 av = *(const float4*)(as + (wm*2 + mi)*512 + (q16*2 + kk8)*128 + lane*4);
                    afr[mi][0] = __float_as_uint(av.x);
                    afr[mi][1] = __float_as_uint(av.y);
                    afr[mi][2] = __float_as_uint(av.z);
                    afr[mi][3] = __float_as_uint(av.w);
                }
                #pragma unroll
                for (int mi = 0; mi < 2; mi++)
                    #pragma unroll
                    for (int ni = 0; ni < 8; ni++) {
                        uint32_t b0 = __float_as_uint(kk8 ? bv[ni].z : bv[ni].x);
                        uint32_t b1 = __float_as_uint(kk8 ? bv[ni].w : bv[ni].y);
                        mma_tf32(acc[mi][ni], afr[mi], b0, b1);
                    }
            }
        }
        s = (s + 1) % NSTG;
    }

    // ---- fused RoPE (warp tile spans exactly one head) ----
    if (mode & 1) {
        #pragma unroll
        for (int mi = 0; mi < 2; mi++) {
            int ra = by*128 + m_warp + mi*16 + g;
            int pa = ra & (SEQ-1);
            int pb = (ra + 8) & (SEQ-1);
            #pragma unroll
            for (int ni = 0; ni < 4; ni++) {
                int i0 = ni*8 + tg*2;
                float ca0 = g_cos[pa*32 + i0],   sa0 = g_sin[pa*32 + i0];
                float ca1 = g_cos[pa*32 + i0+1], sa1 = g_sin[pa*32 + i0+1];
                float cb0 = g_cos[pb*32 + i0],   sb0 = g_sin[pb*32 + i0];
                float cb1 = g_cos[pb*32 + i0+1], sb1 = g_sin[pb*32 + i0+1];
                float x1, x2;
                x1 = acc[mi][ni][0]; x2 = acc[mi][ni+4][0];
                acc[mi][ni][0] = x1*ca0 - x2*sa0; acc[mi][ni+4][0] = x1*sa0 + x2*ca0;
                x1 = acc[mi][ni][1]; x2 = acc[mi][ni+4][1];
                acc[mi][ni][1] = x1*ca1 - x2*sa1; acc[mi][ni+4][1] = x1*sa1 + x2*ca1;
                x1 = acc[mi][ni][2]; x2 = acc[mi][ni+4][2];
                acc[mi][ni][2] = x1*cb0 - x2*sb0; acc[mi][ni+4][2] = x1*sb0 + x2*cb0;
                x1 = acc[mi][ni][3]; x2 = acc[mi][ni+4][3];
                acc[mi][ni][3] = x1*cb1 - x2*sb1; acc[mi][ni+4][3] = x1*sb1 + x2*cb1;
            }
        }
    }

    float mul = (mode & 2) ? 0.125f : 1.0f;
    size_t rowbase = (size_t)by * 128 + m_warp + g;
    int colbase = cb * 128 + n_warp + tg*2;
    if (mode & 4) {
        #pragma unroll
        for (int mi = 0; mi < 2; mi++) {
            size_t r0 = rowbase + mi*16;
            #pragma unroll
            for (int ni = 0; ni < 8; ni++) {
                int c = colbase + ni*8;
                float l0, l1, l2, l3;
                uint32_t h01 = pack_bf16(acc[mi][ni][0]*mul, acc[mi][ni][1]*mul, &l0, &l1);
                uint32_t h23 = pack_bf16(acc[mi][ni][2]*mul, acc[mi][ni][3]*mul, &l2, &l3);
                *(uint32_t*)&Chb[r0*N + c]     = h01;
                *(uint32_t*)&Chb[(r0+8)*N + c] = h23;
                float d0, d1;
                *(uint32_t*)&Clb[r0*N + c]     = pack_bf16(l0, l1, &d0, &d1);
                *(uint32_t*)&Clb[(r0+8)*N + c] = pack_bf16(l2, l3, &d0, &d1);
            }
        }
    } else {
        #pragma unroll
        for (int mi = 0; mi < 2; mi++) {
            size_t r0 = rowbase + mi*16;
            #pragma unroll
            for (int ni = 0; ni < 8; ni++) {
                int c = colbase + ni*8;
                *(float2*)&Cf[r0*N + c]     = make_float2(acc[mi][ni][0], acc[mi][ni][1]);
                *(float2*)&Cf[(r0+8)*N + c] = make_float2(acc[mi][ni][2], acc[mi][ni][3]);
            }
        }
    }
}

// Fused QKV projection + RoPE + bf16-split. grid=(24,32)
__global__ __launch_bounds__(256) void qkv_kernel() {
    int bx = blockIdx.x;
    const float* B; __nv_bfloat16 *Ch, *Cl; int N, cb, mode;
    if (bx < 16)      { B = g_wqp; Ch = g_Qhb; Cl = g_Qlb; N = QDIM;  cb = bx;      mode = 7; }
    else if (bx < 20) { B = g_wkp; Ch = g_Khb; Cl = g_Klb; N = KVDIM; cb = bx - 16; mode = 5; }
    else              { B = g_wvp; Ch = g_Vhb; Cl = g_Vlb; N = KVDIM; cb = bx - 20; mode = 4; }
    gemm_body(g_xp, B, nullptr, Ch, Cl, N, blockIdx.y, cb, mode);
}

// Output projection. grid=(16,32)
__global__ __launch_bounds__(256) void outproj_kernel(float* __restrict__ out) {
    gemm_body(g_Apk, g_wop, out, nullptr, nullptr, DMODEL, blockIdx.y, blockIdx.x, 0);
}

// ---------------------------------------------------------------------------
// Flash attention v5: 3xBF16 + ldmatrix, q-tile 128, 8 warps, double-buffered
// K/V, dedicated P smem. Epilogue writes fragment-packed tf32 A directly.
// ---------------------------------------------------------------------------
#define QP 72
#define QH_B 0
#define QL_B (128*QP)
#define ST_B (2*128*QP)
#define SS   (4*64*QP)
#define KH_B(s) (ST_B + (s)*SS)
#define KL_B(s) (KH_B(s) + 64*QP)
#define VH_B(s) (KH_B(s) + 2*64*QP)
#define VL_B(s) (KH_B(s) + 3*64*QP)
#define PH_B (ST_B + 2*SS)
#define PL_B (PH_B + 128*QP)
#define FL4_SMEM ((PL_B + 128*QP)*2)   // 147456 B

__global__ __launch_bounds__(256) void flash4() {
    extern __shared__ __nv_bfloat16 smh[];

    int qt = blockIdx.x;
    int bh = blockIdx.y;
    int b = bh >> 5, h = bh & 31, gkv = h >> 2;
    int tid = threadIdx.x;
    int lane = tid & 31, warp = tid >> 5;
    int g = lane >> 2, tg = lane & 3;
    int m0 = warp * 16;

    const __nv_bfloat16* Qhb = g_Qhb + ((size_t)b*SEQ + qt*128)*QDIM + h*64;
    const __nv_bfloat16* Qlb = g_Qlb + ((size_t)b*SEQ + qt*128)*QDIM + h*64;
    const __nv_bfloat16* Khb = g_Khb + (size_t)b*SEQ*KVDIM + gkv*64;
    const __nv_bfloat16* Klb = g_Klb + (size_t)b*SEQ*KVDIM + gkv*64;
    const __nv_bfloat16* Vhb = g_Vhb + (size_t)b*SEQ*KVDIM + gkv*64;
    const __nv_bfloat16* Vlb = g_Vlb + (size_t)b*SEQ*KVDIM + gkv*64;

    #pragma unroll
    for (int j = 0; j < 8; j++) {
        int ci = tid + j*256;
        int arr = ci >> 10, rem = ci & 1023;
        int r = rem >> 3, c = rem & 7;
        cp_async16(&smh[(arr ? QL_B : QH_B) + r*QP + c*8],
                   (arr ? Qlb : Qhb) + (size_t)r*QDIM + c*8);
    }
    #pragma unroll
    for (int j = 0; j < 8; j++) {
        int ci = tid + j*256;
        int arr = ci >> 9, rem = ci & 511;
        int r = rem >> 3, c = rem & 7;
        size_t go = (size_t)r*KVDIM + c*8;
        const __nv_bfloat16* src = (arr == 0) ? Khb : (arr == 1) ? Klb : (arr == 2) ? Vhb : Vlb;
        int base = (arr == 0) ? KH_B(0) : (arr == 1) ? KL_B(0) : (arr == 2) ? VH_B(0) : VL_B(0);
        cp_async16(&smh[base + r*QP + c*8], src + go);
    }
    cp_commit();

    float m_i[2] = {-FLT_MAX, -FLT_MAX};
    float l_i[2] = {0.f, 0.f};
    float o[8][4];
    #pragma unroll
    for (int nf = 0; nf < 8; nf++)
        #pragma unroll
        for (int c = 0; c < 4; c++) o[nf][c] = 0.f;

    int ktmax = (128*qt + 16*warp + 15) >> 6;
    int kt_end = 2*qt + 1;
    int lrow = lane & 15, lcol = (lane >> 4) * 8;

    for (int kt = 0; kt <= kt_end; kt++) {
        int st = kt & 1;
        __syncthreads();
        if (kt < kt_end) {
            int nx = st ^ 1;
            #pragma unroll
            for (int j = 0; j < 8; j++) {
                int ci = tid + j*256;
                int arr = ci >> 9, rem = ci & 511;
                int r = rem >> 3, c = rem & 7;
                size_t go = (size_t)((kt+1)*64 + r)*KVDIM + c*8;
                const __nv_bfloat16* src = (arr == 0) ? Khb : (arr == 1) ? Klb : (arr == 2) ? Vhb : Vlb;
                int base = (arr == 0) ? KH_B(nx) : (arr == 1) ? KL_B(nx) : (arr == 2) ? VH_B(nx) : VL_B(nx);
                cp_async16(&smh[base + r*QP + c*8], src + go);
            }
        }
        cp_commit();
        cp_wait<1>();
        __syncthreads();

        if (kt > ktmax) continue;

        float s[8][4];
        #pragma unroll
        for (int nf = 0; nf < 8; nf++)
            #pragma unroll
            for (int c = 0; c < 4; c++) s[nf][c] = 0.f;

        #pragma unroll
        for (int kc = 0; kc < 4; kc++) {
            int kk = kc * 16;
            uint32_t ah[4], al[4];
            {
                uint32_t ad = (uint32_t)__cvta_generic_to_shared(
                    &smh[QH_B + (m0 + lrow)*QP + kk + lcol]);
                ldmx4(ah, ad);
                ad = (uint32_t)__cvta_generic_to_shared(
                    &smh[QL_B + (m0 + lrow)*QP + kk + lcol]);
                ldmx4(al, ad);
            }
            #pragma unroll
            for (int nb = 0; nb < 4; nb++) {
                uint32_t kh[4], kl[4];
                uint32_t ad = (uint32_t)__cvta_generic_to_shared(
                    &smh[KH_B(st) + (nb*16 + lrow)*QP + kk + lcol]);
                ldmx4(kh, ad);
                ad = (uint32_t)__cvta_generic_to_shared(
                    &smh[KL_B(st) + (nb*16 + lrow)*QP + kk + lcol]);
                ldmx4(kl, ad);
                mma_bf16(s[nb*2],   ah, kh[0], kh[2]);
                mma_bf16(s[nb*2],   ah, kl[0], kl[2]);
                mma_bf16(s[nb*2],   al, kh[0], kh[2]);
                mma_bf16(s[nb*2+1], ah, kh[1], kh[3]);
                mma_bf16(s[nb*2+1], ah, kl[1], kl[3]);
                mma_bf16(s[nb*2+1], al, kh[1], kh[3]);
            }
        }

        if (kt*64 + 63 > 128*qt + 16*warp) {
            int r0l = 128*qt + m0 + g, r1l = r0l + 8;
            #pragma unroll
            for (int nf = 0; nf < 8; nf++) {
                int c0 = kt*64 + nf*8 + 2*tg, c1 = c0 + 1;
                if (c0 > r0l) s[nf][0] = -FLT_MAX;
                if (c1 > r0l) s[nf][1] = -FLT_MAX;
                if (c0 > r1l) s[nf][2] = -FLT_MAX;
                if (c1 > r1l) s[nf][3] = -FLT_MAX;
            }
        }

        float rm0 = -FLT_MAX, rm1 = -FLT_MAX;
        #pragma unroll
        for (int nf = 0; nf < 8; nf++) {
            rm0 = fmaxf(rm0, fmaxf(s[nf][0], s[nf][1]));
            rm1 = fmaxf(rm1, fmaxf(s[nf][2], s[nf][3]));
        }
        rm0 = fmaxf(rm0, __shfl_xor_sync(0xffffffffu, rm0, 1));
        rm0 = fmaxf(rm0, __shfl_xor_sync(0xffffffffu, rm0, 2));
        rm1 = fmaxf(rm1, __shfl_xor_sync(0xffffffffu, rm1, 1));
        rm1 = fmaxf(rm1, __shfl_xor_sync(0xffffffffu, rm1, 2));
        float mn0 = fmaxf(m_i[0], rm0), mn1 = fmaxf(m_i[1], rm1);
        float fac0 = __expf(m_i[0] - mn0), fac1 = __expf(m_i[1] - mn1);
        m_i[0] = mn0; m_i[1] = mn1;
        float rs0 = 0.f, rs1 = 0.f;
        #pragma unroll
        for (int nf = 0; nf < 8; nf++) {
            s[nf][0] = __expf(s[nf][0] - mn0); rs0 += s[nf][0];
            s[nf][1] = __expf(s[nf][1] - mn0); rs0 += s[nf][1];
            s[nf][2] = __expf(s[nf][2] - mn1); rs1 += s[nf][2];
            s[nf][3] = __expf(s[nf][3] - mn1); rs1 += s[nf][3];
        }
        rs0 += __shfl_xor_sync(0xffffffffu, rs0, 1);
        rs0 += __shfl_xor_sync(0xffffffffu, rs0, 2);
        rs1 += __shfl_xor_sync(0xffffffffu, rs1, 1);
        rs1 += __shfl_xor_sync(0xffffffffu, rs1, 2);
        l_i[0] = l_i[0]*fac0 + rs0;
        l_i[1] = l_i[1]*fac1 + rs1;
        #pragma unroll
        for (int nf = 0; nf < 8; nf++) {
            o[nf][0] *= fac0; o[nf][1] *= fac0;
            o[nf][2] *= fac1; o[nf][3] *= fac1;
        }

        #pragma unroll
        for (int nf = 0; nf < 8; nf++) {
            int cc = nf*8 + 2*tg;
            float l0, l1, l2, l3;
            uint32_t h01 = pack_bf16(s[nf][0], s[nf][1], &l0, &l1);
            uint32_t h23 = pack_bf16(s[nf][2], s[nf][3], &l2, &l3);
            *(uint32_t*)&smh[PH_B + (m0+g)*QP   + cc] = h01;
            *(uint32_t*)&smh[PH_B + (m0+g+8)*QP + cc] = h23;
            float d0, d1;
            *(uint32_t*)&smh[PL_B + (m0+g)*QP   + cc] = pack_bf16(l0, l1, &d0, &d1);
            *(uint32_t*)&smh[PL_B + (m0+g+8)*QP + cc] = pack_bf16(l2, l3, &d0, &d1);
        }
        __syncwarp();

        #pragma unroll
        for (int kc = 0; kc < 4; kc++) {
            int kk = kc * 16;
            uint32_t ph[4], pl[4];
            {
                uint32_t ad = (uint32_t)__cvta_generic_to_shared(
                    &smh[PH_B + (m0 + lrow)*QP + kk + lcol]);
                ldmx4(ph, ad);
                ad = (uint32_t)__cvta_generic_to_shared(
                    &smh[PL_B + (m0 + lrow)*QP + kk + lcol]);
                ldmx4(pl, ad);
            }
            #pragma unroll
            for (int nb = 0; nb < 4; nb++) {
                uint32_t vh[4], vl[4];
                uint32_t ad = (uint32_t)__cvta_generic_to_shared(
                    &smh[VH_B(st) + (kk + lrow)*QP + nb*16 + lcol]);
                ldmx4t(vh, ad);
                ad = (uint32_t)__cvta_generic_to_shared(
                    &smh[VL_B(st) + (kk + lrow)*QP + nb*16 + lcol]);
                ldmx4t(vl, ad);
                mma_bf16(o[nb*2],   ph, vh[0], vh[1]);
                mma_bf16(o[nb*2],   ph, vl[0], vl[1]);
                mma_bf16(o[nb*2],   pl, vh[0], vh[1]);
                mma_bf16(o[nb*2+1], ph, vh[2], vh[3]);
                mma_bf16(o[nb*2+1], ph, vl[2], vl[3]);
                mma_bf16(o[nb*2+1], pl, vh[2], vh[3]);
            }
        }
    }

    // ---- finalize + fused fragment-pack (writes packA layout directly) ----
    float inv0 = 1.0f / l_i[0], inv1 = 1.0f / l_i[1];
    #pragma unroll
    for (int nf = 0; nf < 8; nf++) {
        o[nf][0] *= inv0; o[nf][1] *= inv0;
        o[nf][2] *= inv1; o[nf][3] *= inv1;
    }

    // Fragment block row index over the full token space
    int Mb = b*(SEQ/16) + qt*8 + warp;
    int sel = tg & 1;
    int srcA = (lane & ~3) | (tg >> 1);
    int srcB = srcA | 2;
    #pragma unroll
    for (int nf = 0; nf < 8; nf++) {
        float va0 = __shfl_sync(0xffffffffu, o[nf][0], srcA);
        float va1 = __shfl_sync(0xffffffffu, o[nf][1], srcA);
        float va2 = __shfl_sync(0xffffffffu, o[nf][2], srcA);
        float va3 = __shfl_sync(0xffffffffu, o[nf][3], srcA);
        float vb0 = __shfl_sync(0xffffffffu, o[nf][0], srcB);
        float vb1 = __shfl_sync(0xffffffffu, o[nf][1], srcB);
        float vb2 = __shfl_sync(0xffffffffu, o[nf][2], srcB);
        float vb3 = __shfl_sync(0xffffffffu, o[nf][3], srcB);
        float x = sel ? va1 : va0;   // (row g,   col tg)
        float y = sel ? va3 : va2;   // (row g+8, col tg)
        float z = sel ? vb1 : vb0;   // (row g,   col tg+4)
        float w = sel ? vb3 : vb2;   // (row g+8, col tg+4)
        int Kb = h*8 + nf;
        size_t off = (((size_t)Mb*(QDIM/8) + Kb)*32 + lane)*4;
        *(float4*)(g_Apk + off) = make_float4(tf32f(x), tf32f(y), tf32f(z), tf32f(w));
    }
}

// ---------------------------------------------------------------------------
extern "C" void kernel_launch(void* const* d_in, const int* in_sizes, int n_in,
                              void* d_out, int out_size) {
    (void)in_sizes; (void)n_in; (void)out_size;
    const float* x  = (const float*)d_in[0];
    const float* wq = (const float*)d_in[1];
    const float* wk = (const float*)d_in[2];
    const float* wv = (const float*)d_in[3];
    const float* wo = (const float*)d_in[4];
    float* out = (float*)d_out;

    float *xp, *wqp, *wkp, *wvp, *wop;
    cudaGetSymbolAddress((void**)&xp,  g_xp);
    cudaGetSymbolAddress((void**)&wqp, g_wqp);
    cudaGetSymbolAddress((void**)&wkp, g_wkp);
    cudaGetSymbolAddress((void**)&wvp, g_wvp);
    cudaGetSymbolAddress((void**)&wop, g_wop);

    static int attr_set = 0;
    if (!attr_set) {
        cudaFuncSetAttribute(flash4, cudaFuncAttributeMaxDynamicSharedMemorySize, FL4_SMEM);
        cudaFuncSetAttribute(qkv_kernel, cudaFuncAttributeMaxDynamicSharedMemorySize, GEMM_SMEM);
        cudaFuncSetAttribute(outproj_kernel, cudaFuncAttributeMaxDynamicSharedMemorySize, GEMM_SMEM);
        attr_set = 1;
    }

    rope_table_kernel<<<(SEQ*32 + 255)/256, 256>>>();

    packA_kernel<<<(TOKENS/16)*(DMODEL/8)*32/256, 256>>>(x,  xp,  TOKENS, DMODEL);
    packB_kernel<<<(QDIM/8)*(DMODEL/16)*32/256,  256>>>(wq, wqp, DMODEL, QDIM);
    packB_kernel<<<(KVDIM/8)*(DMODEL/16)*32/256, 256>>>(wk, wkp, DMODEL, KVDIM);
    packB_kernel<<<(KVDIM/8)*(DMODEL/16)*32/256, 256>>>(wv, wvp, DMODEL, KVDIM);
    packB_kernel<<<(DMODEL/8)*(QDIM/16)*32/256,  256>>>(wo, wop, QDIM, DMODEL);

    qkv_kernel<<<dim3(24, TOKENS/128), 256, GEMM_SMEM>>>();

    flash4<<<dim3(SEQ/128, BATCH*NH), 256, FL4_SMEM>>>();

    outproj_kernel<<<dim3(DMODEL/128, TOKENS/128), 256, GEMM_SMEM>>>(out);
}

// round 17
// speedup vs baseline: 1.0741x; 1.0741x over previous
#include <cuda_runtime.h>
#include <cuda_bf16.h>
#include <math.h>
#include <float.h>
#include <stdint.h>

// Problem constants
#define BATCH 2
#define SEQ   2048
#define DMODEL 2048
#define NH    32
#define NKV   8
#define REP   4
#define HD    64
#define TOKENS (BATCH*SEQ)   // 4096
#define QDIM  (NH*HD)        // 2048
#define KVDIM (NKV*HD)       // 512

// Scratch (device globals: allocation-free)
__device__ __nv_bfloat16 g_Qhb[TOKENS*QDIM],  g_Qlb[TOKENS*QDIM];   // pre-scaled bf16 split Q
__device__ __nv_bfloat16 g_Khb[TOKENS*KVDIM], g_Klb[TOKENS*KVDIM];
__device__ __nv_bfloat16 g_Vhb[TOKENS*KVDIM], g_Vlb[TOKENS*KVDIM];
// fragment-packed, tf32-rounded GEMM operands
__device__ float g_xp[TOKENS*DMODEL];
__device__ float g_wqp[DMODEL*QDIM];
__device__ float g_wkp[DMODEL*KVDIM];
__device__ float g_wvp[DMODEL*KVDIM];
__device__ float g_wop[QDIM*DMODEL];
__device__ float g_Apk[TOKENS*QDIM];   // written directly by flash epilogue
__device__ float g_cos[SEQ*(HD/2)];
__device__ float g_sin[SEQ*(HD/2)];

__device__ __forceinline__ uint32_t f2tf32(float x) {
    uint32_t r;
    asm("cvt.rna.tf32.f32 %0, %1;" : "=r"(r) : "f"(x));
    return r;
}
__device__ __forceinline__ float tf32f(float x) {
    return __uint_as_float(f2tf32(x));
}
__device__ __forceinline__ void mma_tf32(float* c, const uint32_t* a, uint32_t b0, uint32_t b1) {
    asm volatile("mma.sync.aligned.m16n8k8.row.col.f32.tf32.tf32.f32 "
                 "{%0,%1,%2,%3}, {%4,%5,%6,%7}, {%8,%9}, {%0,%1,%2,%3};"
                 : "+f"(c[0]), "+f"(c[1]), "+f"(c[2]), "+f"(c[3])
                 : "r"(a[0]), "r"(a[1]), "r"(a[2]), "r"(a[3]), "r"(b0), "r"(b1));
}
__device__ __forceinline__ void mma_bf16(float* c, const uint32_t* a, uint32_t b0, uint32_t b1) {
    asm volatile("mma.sync.aligned.m16n8k16.row.col.f32.bf16.bf16.f32 "
                 "{%0,%1,%2,%3}, {%4,%5,%6,%7}, {%8,%9}, {%0,%1,%2,%3};"
                 : "+f"(c[0]), "+f"(c[1]), "+f"(c[2]), "+f"(c[3])
                 : "r"(a[0]), "r"(a[1]), "r"(a[2]), "r"(a[3]), "r"(b0), "r"(b1));
}
__device__ __forceinline__ void ldmx4(uint32_t* r, uint32_t addr) {
    asm volatile("ldmatrix.sync.aligned.m8n8.x4.shared.b16 {%0,%1,%2,%3}, [%4];"
                 : "=r"(r[0]), "=r"(r[1]), "=r"(r[2]), "=r"(r[3]) : "r"(addr));
}
__device__ __forceinline__ void ldmx4t(uint32_t* r, uint32_t addr) {
    asm volatile("ldmatrix.sync.aligned.m8n8.x4.trans.shared.b16 {%0,%1,%2,%3}, [%4];"
                 : "=r"(r[0]), "=r"(r[1]), "=r"(r[2]), "=r"(r[3]) : "r"(addr));
}
__device__ __forceinline__ void cp_async16(void* smem_dst, const void* gmem_src) {
    uint32_t s = (uint32_t)__cvta_generic_to_shared(smem_dst);
    asm volatile("cp.async.cg.shared.global [%0], [%1], 16;" :: "r"(s), "l"(gmem_src));
}
__device__ __forceinline__ void cp_commit() {
    asm volatile("cp.async.commit_group;");
}
template<int N> __device__ __forceinline__ void cp_wait() {
    asm volatile("cp.async.wait_group %0;" :: "n"(N));
}
__device__ __forceinline__ uint32_t pack_bf16(float a, float b, float* ra, float* rb) {
    __nv_bfloat16 ha = __float2bfloat16(a);
    __nv_bfloat16 hb = __float2bfloat16(b);
    *ra = a - __bfloat162float(ha);
    *rb = b - __bfloat162float(hb);
    uint32_t lo = (uint32_t)__bfloat16_as_ushort(ha);
    uint32_t hi = (uint32_t)__bfloat16_as_ushort(hb);
    return lo | (hi << 16);
}

// ---------------------------------------------------------------------------
// Fragment packers (include tf32 rounding).
// ---------------------------------------------------------------------------
__global__ void packA_kernel(const float* __restrict__ in, float* __restrict__ out,
                             int R, int C) {
    int idx = blockIdx.x * blockDim.x + threadIdx.x;
    int total = (R >> 4) * (C >> 3) * 32;
    if (idx >= total) return;
    int l  = idx & 31;
    int t2 = idx >> 5;
    int Kb = t2 % (C >> 3);
    int Mb = t2 / (C >> 3);
    int g = l >> 2, tg = l & 3;
    const float* src = in + (size_t)(Mb*16 + g)*C + Kb*8 + tg;
    float4 v;
    v.x = tf32f(src[0]);
    v.y = tf32f(src[(size_t)8*C]);
    v.z = tf32f(src[4]);
    v.w = tf32f(src[(size_t)8*C + 4]);
    *(float4*)(out + (size_t)idx*4) = v;
}

__global__ void packB_kernel(const float* __restrict__ in, float* __restrict__ out,
                             int K, int N) {
    int idx = blockIdx.x * blockDim.x + threadIdx.x;
    int total = (N >> 3) * (K >> 4) * 32;
    if (idx >= total) return;
    int l  = idx & 31;
    int t2 = idx >> 5;
    int Kp = t2 % (K >> 4);
    int Nb = t2 / (K >> 4);
    int g = l >> 2, tg = l & 3;
    const float* src = in + (size_t)(Kp*16 + tg)*N + Nb*8 + g;
    float4 v;
    v.x = tf32f(src[0]);
    v.y = tf32f(src[(size_t)4*N]);
    v.z = tf32f(src[(size_t)8*N]);
    v.w = tf32f(src[(size_t)12*N]);
    *(float4*)(out + (size_t)idx*4) = v;
}

// ---------------------------------------------------------------------------
// RoPE tables
// ---------------------------------------------------------------------------
__global__ void rope_table_kernel() {
    int idx = blockIdx.x * blockDim.x + threadIdx.x;
    if (idx >= SEQ*(HD/2)) return;
    int pos = idx >> 5;
    int i   = idx & 31;
    double expo = (2.0 * i) / 64.0;
    float invf = (float)(1.0 / pow(10000.0, expo));
    float fr = (float)pos * invf;
    double a = (double)fr;
    g_cos[idx] = (float)cos(a);
    g_sin[idx] = (float)sin(a);
}

// ---------------------------------------------------------------------------
// Pipelined tf32 GEMM on fragment-packed operands (R14 BK=16 version).
//   mode bit0: RoPE   bit1: scale 0.125   bit2: split into bf16 hi/lo (Chb,Clb)
// smem/stage: A 2048 floats ([mb8][k8x2][lane][4]), B 2048 ([nb16][lane][4]).
// ---------------------------------------------------------------------------
#define GK 2048
#define NSTG 3
#define ASTG2 2048
#define BSTG2 2048
#define GEMM_SMEM (NSTG*(ASTG2+BSTG2)*4)   // 49152 B

__device__ __forceinline__ void gemm_body(const float* __restrict__ Apk,
                                          const float* __restrict__ Bpk,
                                          float* __restrict__ Cf,
                                          __nv_bfloat16* __restrict__ Chb,
                                          __nv_bfloat16* __restrict__ Clb,
                                          int N, int by, int cb, int mode) {
    extern __shared__ float sm[];
    float* As = sm;
    float* Bs = sm + NSTG*ASTG2;

    int tid  = threadIdx.x;
    int lane = tid & 31, warp = tid >> 5;
    int wm = warp & 3, wn = warp >> 2;
    int m_warp = wm * 32, n_warp = wn * 64;
    int g  = lane >> 2;
    int tg = lane & 3;

    int a_mb = tid >> 5, a_l = tid & 31;     // A: 8 m-blocks x 32 lanes
    int b_nb = tid >> 4, b_sub = tid & 15;   // B: 16 n-blocks x 16 subs

    const float* Abase = Apk + (((size_t)(by*8 + a_mb))*(GK/8))*128 + a_l*4;
    const float* Bbase = Bpk + (((size_t)(cb*16 + b_nb))*(GK/16))*128 + b_sub*8;

    float acc[2][8][4];
    #pragma unroll
    for (int mi = 0; mi < 2; mi++)
        #pragma unroll
        for (int ni = 0; ni < 8; ni++)
            #pragma unroll
            for (int c = 0; c < 4; c++) acc[mi][ni][c] = 0.f;

    #pragma unroll
    for (int s = 0; s < NSTG-1; s++) {
        float* as = As + s*ASTG2;
        float* bs = Bs + s*BSTG2;
        cp_async16(&as[a_mb*256 + a_l*4],       Abase + (size_t)(2*s)*128);
        cp_async16(&as[a_mb*256 + 128 + a_l*4], Abase + (size_t)(2*s+1)*128);
        cp_async16(&bs[b_nb*128 + b_sub*8],     Bbase + (size_t)s*128);
        cp_async16(&bs[b_nb*128 + b_sub*8 + 4], Bbase + (size_t)s*128 + 4);
        cp_commit();
    }

    const int NITER = GK / 16;
    int s = 0;
    for (int it = 0; it < NITER; it++) {
        cp_wait<NSTG-2>();
        __syncthreads();

        int itpre = it + NSTG - 1;
        if (itpre < NITER) {
            int sp = itpre % NSTG;
            float* as = As + sp*ASTG2;
            float* bs = Bs + sp*BSTG2;
            cp_async16(&as[a_mb*256 + a_l*4],       Abase + (size_t)(2*itpre)*128);
            cp_async16(&as[a_mb*256 + 128 + a_l*4], Abase + (size_t)(2*itpre+1)*128);
            cp_async16(&bs[b_nb*128 + b_sub*8],     Bbase + (size_t)itpre*128);
            cp_async16(&bs[b_nb*128 + b_sub*8 + 4], Bbase + (size_t)itpre*128 + 4);
        }
        cp_commit();

        const float* as = As + s*ASTG2;
        const float* bs = Bs + s*BSTG2;

        float4 bv[8];
        #pragma unroll
        for (int ni = 0; ni < 8; ni++)
            bv[ni] = *(const float4*)(bs + (n_warp/8 + ni)*128 + lane*4);

        #pragma unroll
        for (int kk8 = 0; kk8 < 2; kk8++) {
            uint32_t afr[2][4];
            #pragma unroll
            for (int mi = 0; mi < 2; mi++) {
                float4 av = *(const float4*)(as + (wm*2 + mi)*256 + kk8*128 + lane*4);
                afr[mi][0] = __float_as_uint(av.x);
                afr[mi][1] = __float_as_uint(av.y);
                afr[mi][2] = __float_as_uint(av.z);
                afr[mi][3] = __float_as_uint(av.w);
            }
            #pragma unroll
            for (int mi = 0; mi < 2; mi++)
                #pragma unroll
                for (int ni = 0; ni < 8; ni++) {
                    uint32_t b0 = __float_as_uint(kk8 ? bv[ni].z : bv[ni].x);
                    uint32_t b1 = __float_as_uint(kk8 ? bv[ni].w : bv[ni].y);
                    mma_tf32(acc[mi][ni], afr[mi], b0, b1);
                }
        }
        s = (s + 1) % NSTG;
    }

    // ---- fused RoPE (warp tile spans exactly one head) ----
    if (mode & 1) {
        #pragma unroll
        for (int mi = 0; mi < 2; mi++) {
            int ra = by*128 + m_warp + mi*16 + g;
            int pa = ra & (SEQ-1);
            int pb = (ra + 8) & (SEQ-1);
            #pragma unroll
            for (int ni = 0; ni < 4; ni++) {
                int i0 = ni*8 + tg*2;
                float ca0 = g_cos[pa*32 + i0],   sa0 = g_sin[pa*32 + i0];
                float ca1 = g_cos[pa*32 + i0+1], sa1 = g_sin[pa*32 + i0+1];
                float cb0 = g_cos[pb*32 + i0],   sb0 = g_sin[pb*32 + i0];
                float cb1 = g_cos[pb*32 + i0+1], sb1 = g_sin[pb*32 + i0+1];
                float x1, x2;
                x1 = acc[mi][ni][0]; x2 = acc[mi][ni+4][0];
                acc[mi][ni][0] = x1*ca0 - x2*sa0; acc[mi][ni+4][0] = x1*sa0 + x2*ca0;
                x1 = acc[mi][ni][1]; x2 = acc[mi][ni+4][1];
                acc[mi][ni][1] = x1*ca1 - x2*sa1; acc[mi][ni+4][1] = x1*sa1 + x2*ca1;
                x1 = acc[mi][ni][2]; x2 = acc[mi][ni+4][2];
                acc[mi][ni][2] = x1*cb0 - x2*sb0; acc[mi][ni+4][2] = x1*sb0 + x2*cb0;
                x1 = acc[mi][ni][3]; x2 = acc[mi][ni+4][3];
                acc[mi][ni][3] = x1*cb1 - x2*sb1; acc[mi][ni+4][3] = x1*sb1 + x2*cb1;
            }
        }
    }

    float mul = (mode & 2) ? 0.125f : 1.0f;
    size_t rowbase = (size_t)by * 128 + m_warp + g;
    int colbase = cb * 128 + n_warp + tg*2;
    if (mode & 4) {
        #pragma unroll
        for (int mi = 0; mi < 2; mi++) {
            size_t r0 = rowbase + mi*16;
            #pragma unroll
            for (int ni = 0; ni < 8; ni++) {
                int c = colbase + ni*8;
                float l0, l1, l2, l3;
                uint32_t h01 = pack_bf16(acc[mi][ni][0]*mul, acc[mi][ni][1]*mul, &l0, &l1);
                uint32_t h23 = pack_bf16(acc[mi][ni][2]*mul, acc[mi][ni][3]*mul, &l2, &l3);
                *(uint32_t*)&Chb[r0*N + c]     = h01;
                *(uint32_t*)&Chb[(r0+8)*N + c] = h23;
                float d0, d1;
                *(uint32_t*)&Clb[r0*N + c]     = pack_bf16(l0, l1, &d0, &d1);
                *(uint32_t*)&Clb[(r0+8)*N + c] = pack_bf16(l2, l3, &d0, &d1);
            }
        }
    } else {
        #pragma unroll
        for (int mi = 0; mi < 2; mi++) {
            size_t r0 = rowbase + mi*16;
            #pragma unroll
            for (int ni = 0; ni < 8; ni++) {
                int c = colbase + ni*8;
                *(float2*)&Cf[r0*N + c]     = make_float2(acc[mi][ni][0], acc[mi][ni][1]);
                *(float2*)&Cf[(r0+8)*N + c] = make_float2(acc[mi][ni][2], acc[mi][ni][3]);
            }
        }
    }
}

// Fused QKV projection + RoPE + bf16-split. grid=(24,32)
__global__ __launch_bounds__(256) void qkv_kernel() {
    int bx = blockIdx.x;
    const float* B; __nv_bfloat16 *Ch, *Cl; int N, cb, mode;
    if (bx < 16)      { B = g_wqp; Ch = g_Qhb; Cl = g_Qlb; N = QDIM;  cb = bx;      mode = 7; }
    else if (bx < 20) { B = g_wkp; Ch = g_Khb; Cl = g_Klb; N = KVDIM; cb = bx - 16; mode = 5; }
    else              { B = g_wvp; Ch = g_Vhb; Cl = g_Vlb; N = KVDIM; cb = bx - 20; mode = 4; }
    gemm_body(g_xp, B, nullptr, Ch, Cl, N, blockIdx.y, cb, mode);
}

// Output projection. grid=(16,32)
__global__ __launch_bounds__(256) void outproj_kernel(float* __restrict__ out) {
    gemm_body(g_Apk, g_wop, out, nullptr, nullptr, DMODEL, blockIdx.y, blockIdx.x, 0);
}

// ---------------------------------------------------------------------------
// Flash attention v5: 3xBF16 + ldmatrix, q-tile 128, 8 warps, double-buffered
// K/V, dedicated P smem. Epilogue writes fragment-packed tf32 A directly.
// ---------------------------------------------------------------------------
#define QP 72
#define QH_B 0
#define QL_B (128*QP)
#define ST_B (2*128*QP)
#define SS   (4*64*QP)
#define KH_B(s) (ST_B + (s)*SS)
#define KL_B(s) (KH_B(s) + 64*QP)
#define VH_B(s) (KH_B(s) + 2*64*QP)
#define VL_B(s) (KH_B(s) + 3*64*QP)
#define PH_B (ST_B + 2*SS)
#define PL_B (PH_B + 128*QP)
#define FL4_SMEM ((PL_B + 128*QP)*2)   // 147456 B

__global__ __launch_bounds__(256) void flash4() {
    extern __shared__ __nv_bfloat16 smh[];

    int qt = blockIdx.x;
    int bh = blockIdx.y;
    int b = bh >> 5, h = bh & 31, gkv = h >> 2;
    int tid = threadIdx.x;
    int lane = tid & 31, warp = tid >> 5;
    int g = lane >> 2, tg = lane & 3;
    int m0 = warp * 16;

    const __nv_bfloat16* Qhb = g_Qhb + ((size_t)b*SEQ + qt*128)*QDIM + h*64;
    const __nv_bfloat16* Qlb = g_Qlb + ((size_t)b*SEQ + qt*128)*QDIM + h*64;
    const __nv_bfloat16* Khb = g_Khb + (size_t)b*SEQ*KVDIM + gkv*64;
    const __nv_bfloat16* Klb = g_Klb + (size_t)b*SEQ*KVDIM + gkv*64;
    const __nv_bfloat16* Vhb = g_Vhb + (size_t)b*SEQ*KVDIM + gkv*64;
    const __nv_bfloat16* Vlb = g_Vlb + (size_t)b*SEQ*KVDIM + gkv*64;

    #pragma unroll
    for (int j = 0; j < 8; j++) {
        int ci = tid + j*256;
        int arr = ci >> 10, rem = ci & 1023;
        int r = rem >> 3, c = rem & 7;
        cp_async16(&smh[(arr ? QL_B : QH_B) + r*QP + c*8],
                   (arr ? Qlb : Qhb) + (size_t)r*QDIM + c*8);
    }
    #pragma unroll
    for (int j = 0; j < 8; j++) {
        int ci = tid + j*256;
        int arr = ci >> 9, rem = ci & 511;
        int r = rem >> 3, c = rem & 7;
        size_t go = (size_t)r*KVDIM + c*8;
        const __nv_bfloat16* src = (arr == 0) ? Khb : (arr == 1) ? Klb : (arr == 2) ? Vhb : Vlb;
        int base = (arr == 0) ? KH_B(0) : (arr == 1) ? KL_B(0) : (arr == 2) ? VH_B(0) : VL_B(0);
        cp_async16(&smh[base + r*QP + c*8], src + go);
    }
    cp_commit();

    float m_i[2] = {-FLT_MAX, -FLT_MAX};
    float l_i[2] = {0.f, 0.f};
    float o[8][4];
    #pragma unroll
    for (int nf = 0; nf < 8; nf++)
        #pragma unroll
        for (int c = 0; c < 4; c++) o[nf][c] = 0.f;

    int ktmax = (128*qt + 16*warp + 15) >> 6;
    int kt_end = 2*qt + 1;
    int lrow = lane & 15, lcol = (lane >> 4) * 8;

    for (int kt = 0; kt <= kt_end; kt++) {
        int st = kt & 1;
        __syncthreads();
        if (kt < kt_end) {
            int nx = st ^ 1;
            #pragma unroll
            for (int j = 0; j < 8; j++) {
                int ci = tid + j*256;
                int arr = ci >> 9, rem = ci & 511;
                int r = rem >> 3, c = rem & 7;
                size_t go = (size_t)((kt+1)*64 + r)*KVDIM + c*8;
                const __nv_bfloat16* src = (arr == 0) ? Khb : (arr == 1) ? Klb : (arr == 2) ? Vhb : Vlb;
                int base = (arr == 0) ? KH_B(nx) : (arr == 1) ? KL_B(nx) : (arr == 2) ? VH_B(nx) : VL_B(nx);
                cp_async16(&smh[base + r*QP + c*8], src + go);
            }
        }
        cp_commit();
        cp_wait<1>();
        __syncthreads();

        if (kt > ktmax) continue;

        float s[8][4];
        #pragma unroll
        for (int nf = 0; nf < 8; nf++)
            #pragma unroll
            for (int c = 0; c < 4; c++) s[nf][c] = 0.f;

        #pragma unroll
        for (int kc = 0; kc < 4; kc++) {
            int kk = kc * 16;
            uint32_t ah[4], al[4];
            {
                uint32_t ad = (uint32_t)__cvta_generic_to_shared(
                    &smh[QH_B + (m0 + lrow)*QP + kk + lcol]);
                ldmx4(ah, ad);
                ad = (uint32_t)__cvta_generic_to_shared(
                    &smh[QL_B + (m0 + lrow)*QP + kk + lcol]);
                ldmx4(al, ad);
            }
            #pragma unroll
            for (int nb = 0; nb < 4; nb++) {
                uint32_t kh[4], kl[4];
                uint32_t ad = (uint32_t)__cvta_generic_to_shared(
                    &smh[KH_B(st) + (nb*16 + lrow)*QP + kk + lcol]);
                ldmx4(kh, ad);
                ad = (uint32_t)__cvta_generic_to_shared(
                    &smh[KL_B(st) + (nb*16 + lrow)*QP + kk + lcol]);
                ldmx4(kl, ad);
                mma_bf16(s[nb*2],   ah, kh[0], kh[2]);
                mma_bf16(s[nb*2],   ah, kl[0], kl[2]);
                mma_bf16(s[nb*2],   al, kh[0], kh[2]);
                mma_bf16(s[nb*2+1], ah, kh[1], kh[3]);
                mma_bf16(s[nb*2+1], ah, kl[1], kl[3]);
                mma_bf16(s[nb*2+1], al, kh[1], kh[3]);
            }
        }

        if (kt*64 + 63 > 128*qt + 16*warp) {
            int r0l = 128*qt + m0 + g, r1l = r0l + 8;
            #pragma unroll
            for (int nf = 0; nf < 8; nf++) {
                int c0 = kt*64 + nf*8 + 2*tg, c1 = c0 + 1;
                if (c0 > r0l) s[nf][0] = -FLT_MAX;
                if (c1 > r0l) s[nf][1] = -FLT_MAX;
                if (c0 > r1l) s[nf][2] = -FLT_MAX;
                if (c1 > r1l) s[nf][3] = -FLT_MAX;
            }
        }

        float rm0 = -FLT_MAX, rm1 = -FLT_MAX;
        #pragma unroll
        for (int nf = 0; nf < 8; nf++) {
            rm0 = fmaxf(rm0, fmaxf(s[nf][0], s[nf][1]));
            rm1 = fmaxf(rm1, fmaxf(s[nf][2], s[nf][3]));
        }
        rm0 = fmaxf(rm0, __shfl_xor_sync(0xffffffffu, rm0, 1));
        rm0 = fmaxf(rm0, __shfl_xor_sync(0xffffffffu, rm0, 2));
        rm1 = fmaxf(rm1, __shfl_xor_sync(0xffffffffu, rm1, 1));
        rm1 = fmaxf(rm1, __shfl_xor_sync(0xffffffffu, rm1, 2));
        float mn0 = fmaxf(m_i[0], rm0), mn1 = fmaxf(m_i[1], rm1);
        float fac0 = __expf(m_i[0] - mn0), fac1 = __expf(m_i[1] - mn1);
        m_i[0] = mn0; m_i[1] = mn1;
        float rs0 = 0.f, rs1 = 0.f;
        #pragma unroll
        for (int nf = 0; nf < 8; nf++) {
            s[nf][0] = __expf(s[nf][0] - mn0); rs0 += s[nf][0];
            s[nf][1] = __expf(s[nf][1] - mn0); rs0 += s[nf][1];
            s[nf][2] = __expf(s[nf][2] - mn1); rs1 += s[nf][2];
            s[nf][3] = __expf(s[nf][3] - mn1); rs1 += s[nf][3];
        }
        rs0 += __shfl_xor_sync(0xffffffffu, rs0, 1);
        rs0 += __shfl_xor_sync(0xffffffffu, rs0, 2);
        rs1 += __shfl_xor_sync(0xffffffffu, rs1, 1);
        rs1 += __shfl_xor_sync(0xffffffffu, rs1, 2);
        l_i[0] = l_i[0]*fac0 + rs0;
        l_i[1] = l_i[1]*fac1 + rs1;
        #pragma unroll
        for (int nf = 0; nf < 8; nf++) {
            o[nf][0] *= fac0; o[nf][1] *= fac0;
            o[nf][2] *= fac1; o[nf][3] *= fac1;
        }

        #pragma unroll
        for (int nf = 0; nf < 8; nf++) {
            int cc = nf*8 + 2*tg;
            float l0, l1, l2, l3;
            uint32_t h01 = pack_bf16(s[nf][0], s[nf][1], &l0, &l1);
            uint32_t h23 = pack_bf16(s[nf][2], s[nf][3], &l2, &l3);
            *(uint32_t*)&smh[PH_B + (m0+g)*QP   + cc] = h01;
            *(uint32_t*)&smh[PH_B + (m0+g+8)*QP + cc] = h23;
            float d0, d1;
            *(uint32_t*)&smh[PL_B + (m0+g)*QP   + cc] = pack_bf16(l0, l1, &d0, &d1);
            *(uint32_t*)&smh[PL_B + (m0+g+8)*QP + cc] = pack_bf16(l2, l3, &d0, &d1);
        }
        __syncwarp();

        #pragma unroll
        for (int kc = 0; kc < 4; kc++) {
            int kk = kc * 16;
            uint32_t ph[4], pl[4];
            {
                uint32_t ad = (uint32_t)__cvta_generic_to_shared(
                    &smh[PH_B + (m0 + lrow)*QP + kk + lcol]);
                ldmx4(ph, ad);
                ad = (uint32_t)__cvta_generic_to_shared(
                    &smh[PL_B + (m0 + lrow)*QP + kk + lcol]);
                ldmx4(pl, ad);
            }
            #pragma unroll
            for (int nb = 0; nb < 4; nb++) {
                uint32_t vh[4], vl[4];
                uint32_t ad = (uint32_t)__cvta_generic_to_shared(
                    &smh[VH_B(st) + (kk + lrow)*QP + nb*16 + lcol]);
                ldmx4t(vh, ad);
                ad = (uint32_t)__cvta_generic_to_shared(
                    &smh[VL_B(st) + (kk + lrow)*QP + nb*16 + lcol]);
                ldmx4t(vl, ad);
                mma_bf16(o[nb*2],   ph, vh[0], vh[1]);
                mma_bf16(o[nb*2],   ph, vl[0], vl[1]);
                mma_bf16(o[nb*2],   pl, vh[0], vh[1]);
                mma_bf16(o[nb*2+1], ph, vh[2], vh[3]);
                mma_bf16(o[nb*2+1], ph, vl[2], vl[3]);
                mma_bf16(o[nb*2+1], pl, vh[2], vh[3]);
            }
        }
    }

    // ---- finalize + fused fragment-pack (writes packA layout directly) ----
    float inv0 = 1.0f / l_i[0], inv1 = 1.0f / l_i[1];
    #pragma unroll
    for (int nf = 0; nf < 8; nf++) {
        o[nf][0] *= inv0; o[nf][1] *= inv0;
        o[nf][2] *= inv1; o[nf][3] *= inv1;
    }

    int Mb = b*(SEQ/16) + qt*8 + warp;
    int sel = tg & 1;
    int srcA = (lane & ~3) | (tg >> 1);
    int srcB = srcA | 2;
    #pragma unroll
    for (int nf = 0; nf < 8; nf++) {
        float va0 = __shfl_sync(0xffffffffu, o[nf][0], srcA);
        float va1 = __shfl_sync(0xffffffffu, o[nf][1], srcA);
        float va2 = __shfl_sync(0xffffffffu, o[nf][2], srcA);
        float va3 = __shfl_sync(0xffffffffu, o[nf][3], srcA);
        float vb0 = __shfl_sync(0xffffffffu, o[nf][0], srcB);
        float vb1 = __shfl_sync(0xffffffffu, o[nf][1], srcB);
        float vb2 = __shfl_sync(0xffffffffu, o[nf][2], srcB);
        float vb3 = __shfl_sync(0xffffffffu, o[nf][3], srcB);
        float x = sel ? va1 : va0;
        float y = sel ? va3 : va2;
        float z = sel ? vb1 : vb0;
        float w = sel ? vb3 : vb2;
        int Kb = h*8 + nf;
        size_t off = (((size_t)Mb*(QDIM/8) + Kb)*32 + lane)*4;
        *(float4*)(g_Apk + off) = make_float4(tf32f(x), tf32f(y), tf32f(z), tf32f(w));
    }
}

// ---------------------------------------------------------------------------
extern "C" void kernel_launch(void* const* d_in, const int* in_sizes, int n_in,
                              void* d_out, int out_size) {
    (void)in_sizes; (void)n_in; (void)out_size;
    const float* x  = (const float*)d_in[0];
    const float* wq = (const float*)d_in[1];
    const float* wk = (const float*)d_in[2];
    const float* wv = (const float*)d_in[3];
    const float* wo = (const float*)d_in[4];
    float* out = (float*)d_out;

    float *xp, *wqp, *wkp, *wvp, *wop;
    cudaGetSymbolAddress((void**)&xp,  g_xp);
    cudaGetSymbolAddress((void**)&wqp, g_wqp);
    cudaGetSymbolAddress((void**)&wkp, g_wkp);
    cudaGetSymbolAddress((void**)&wvp, g_wvp);
    cudaGetSymbolAddress((void**)&wop, g_wop);

    static int attr_set = 0;
    if (!attr_set) {
        cudaFuncSetAttribute(flash4, cudaFuncAttributeMaxDynamicSharedMemorySize, FL4_SMEM);
        cudaFuncSetAttribute(qkv_kernel, cudaFuncAttributeMaxDynamicSharedMemorySize, GEMM_SMEM);
        cudaFuncSetAttribute(outproj_kernel, cudaFuncAttributeMaxDynamicSharedMemorySize, GEMM_SMEM);
        attr_set = 1;
    }

    rope_table_kernel<<<(SEQ*32 + 255)/256, 256>>>();

    packA_kernel<<<(TOKENS/16)*(DMODEL/8)*32/256, 256>>>(x,  xp,  TOKENS, DMODEL);
    packB_kernel<<<(QDIM/8)*(DMODEL/16)*32/256,  256>>>(wq, wqp, DMODEL, QDIM);
    packB_kernel<<<(KVDIM/8)*(DMODEL/16)*32/256, 256>>>(wk, wkp, DMODEL, KVDIM);
    packB_kernel<<<(KVDIM/8)*(DMODEL/16)*32/256, 256>>>(wv, wvp, DMODEL, KVDIM);
    packB_kernel<<<(DMODEL/8)*(QDIM/16)*32/256,  256>>>(wo, wop, QDIM, DMODEL);

    qkv_kernel<<<dim3(24, TOKENS/128), 256, GEMM_SMEM>>>();

    flash4<<<dim3(SEQ/128, BATCH*NH), 256, FL4_SMEM>>>();

    outproj_kernel<<<dim3(DMODEL/128, TOKENS/128), 256, GEMM_SMEM>>>(out);
}